// round 17
// baseline (speedup 1.0000x reference)
#include <cuda_runtime.h>
#include <cuda_bf16.h>

// Problem constants
#define TT   12
#define NN   10000
#define FIN  64
#define NH   4
#define CC   32
#define HC   128      // NH*CC
#define TNN  120000   // TT*NN
#define EE   1000000
#define SL0  110000   // first node of time-slice t=11
#define HID  32

// chain parallelization
#define SEGL 17      // steps emitted per block (592*17 = 10064 >= NN)
#define NSEG 592
#define WARM 32      // warmup steps from zero state (contraction: err ~ e^-18 worst-case)

// k_init geometry: grid must cover ALL of g_xacc (2,560,000 floats)
#define INITB 10000          // blocks of 256 -> 2,560,000 threads
#define EAS0  9700           // easum blocks [9700, 9996)
#define EASN  296
#define VAB0  9996           // va/vd blocks [9996, 9998)

// ---------------- scratch (device globals; no allocation allowed) ----------
__device__ float    g_asrc[TNN * 4];        // x[n]·va_h  (all nodes)
__device__ float    g_adst[NN * 4];         // x[n]·vd_h  (slice nodes only)
__device__ float    g_va[NH * FIN];         // W_gat @ att_src (per head)
__device__ float    g_vd[NH * FIN];         // W_gat @ att_dst
__device__ float    g_denom[NN * 4];
__device__ float4   g_xacc[NN * NH * (FIN / 4)];  // per-head weighted x sums
__device__ float    g_gat[NN * HC];         // relu'd GAT output rows
__device__ float    g_pre[(NN + 8) * HC];   // LSTM gate pre-activations (+8 pad rows)
__device__ float    g_hist[NN * HID];       // h state after each step
__device__ float    g_easum;
__device__ float    g_kvec[4];

// ---------------- helpers ---------------------------------------------------
__device__ __forceinline__ float lrelu(float x) { return fmaxf(x, 0.f) + 0.2f * fminf(x, 0.f); }

// ---------------- k_init: zero scratch + easum + va/vd + kvec (fused) --------
// Grid = INITB(10000) x 256: idx in [0, 2.56M) fully covers g_xacc zeroing.
__global__ void k_init(const float* __restrict__ W_edge, const float* __restrict__ att_edge,
                       const float* __restrict__ ea,
                       const float* __restrict__ W_gat,
                       const float* __restrict__ att_src, const float* __restrict__ att_dst) {
    int idx = blockIdx.x * blockDim.x + threadIdx.x;
    if (idx < NN * NH * FIN) ((float*)g_xacc)[idx] = 0.f;   // ALL threads participate
    if (idx < NN * 4) g_denom[idx] = 0.f;
    if (idx < 8 * HC) g_pre[NN * HC + idx] = 0.f;   // zero pad rows
    if (idx == 0) g_easum = 0.f;
    if (idx < 4) {
        float s = 0.f;
        #pragma unroll
        for (int c = 0; c < CC; c++) s += W_edge[idx * CC + c] * att_edge[idx * CC + c];
        g_kvec[idx] = s;
    }
    // va/vd: blocks [VAB0, VAB0+2) -> 512 threads, t = h*64+f for src then dst
    int vb = idx - VAB0 * 256;
    if (vb >= 0 && vb < 2 * NH * FIN) {
        int which = vb >> 8;              // 0 = va, 1 = vd
        int t = vb & 255;
        int h = t >> 6, f = t & 63;
        const float* att = which ? att_dst : att_src;
        float s = 0.f;
        #pragma unroll
        for (int c = 0; c < CC; c++) s = fmaf(W_gat[f * HC + h * CC + c], att[h * CC + c], s);
        (which ? g_vd : g_va)[t] = s;
    }
    // easum: blocks [EAS0, EAS0+EASN) grid-stride over E
    int eb = blockIdx.x - EAS0;
    if (eb >= 0 && eb < EASN) {
        int tid = eb * 256 + threadIdx.x;
        float v = 0.f;
        for (int i = tid; i < EE; i += EASN * 256) v += ea[i];
        #pragma unroll
        for (int o = 16; o; o >>= 1) v += __shfl_down_sync(0xffffffffu, v, o);
        __shared__ float sm[8];
        if ((threadIdx.x & 31) == 0) sm[threadIdx.x >> 5] = v;
        __syncthreads();
        if (threadIdx.x < 8) {
            v = sm[threadIdx.x];
            #pragma unroll
            for (int o = 4; o; o >>= 1) v += __shfl_down_sync(0xffu, v, o);
            if (threadIdx.x == 0) atomicAdd(&g_easum, v);
        }
    }
}

// ---------------- k_alog: attention logits, tiled GEMM, smem weights ---------
// 256 threads: node_l = t>>3 (32 nodes/chunk), out = t&7 (4 src + 4 dst heads).
// va/vd rows live in SHARED (low regs -> high occupancy -> DRAM streaming rate).
#define ANB 32
__global__ void __launch_bounds__(256) k_alog(const float* __restrict__ x) {
    __shared__ float sx[ANB][FIN + 4];       // stride 68 floats: conflict-free
    __shared__ float sWv[8][FIN];            // rows 0-3 = va, 4-7 = vd
    int tid = threadIdx.x;
    int node_l = tid >> 3, out = tid & 7;

    sWv[tid >> 6][tid & 63]       = g_va[tid & 255];
    sWv[4 + (tid >> 6)][tid & 63] = g_vd[tid & 255];
    __syncthreads();

    for (int chunk = blockIdx.x; chunk * ANB < TNN; chunk += gridDim.x) {
        int nb = chunk * ANB;
        const float4* xg = (const float4*)(x + nb * FIN);
        #pragma unroll
        for (int i = 0; i < 2; i++) {
            int t2 = tid + i * 256;          // 0..511 float4 slots
            int nd = t2 >> 4, f4 = t2 & 15;
            *(float4*)&sx[nd][f4 * 4] = xg[t2];
        }
        __syncthreads();

        float s0 = 0.f, s1 = 0.f, s2 = 0.f, s3 = 0.f;
        const float4* xr = (const float4*)sx[node_l];
        const float4* wr = (const float4*)sWv[out];
        #pragma unroll
        for (int q = 0; q < FIN / 4; q++) {
            float4 xv = xr[q];
            float4 wv = wr[q];
            s0 = fmaf(xv.x, wv.x, s0);
            s1 = fmaf(xv.y, wv.y, s1);
            s2 = fmaf(xv.z, wv.z, s2);
            s3 = fmaf(xv.w, wv.w, s3);
        }
        float dot = (s0 + s1) + (s2 + s3);
        int n = nb + node_l;
        if (out < 4) g_asrc[n * 4 + out] = dot;
        else if (n >= SL0) g_adst[(n - SL0) * 4 + (out - 4)] = dot;
        __syncthreads();
    }
}

// ---------------- k_pass2: edge pass accumulating x-space sums ---------------
__device__ __forceinline__ bool edge_fetch(int e, const int* __restrict__ ei,
                                           const float* __restrict__ ea,
                                           int& src, int& dst, float& a) {
    if (e < EE) {
        dst = ei[EE + e];
        if (dst < SL0) return false;
        src = ei[e];
        a = ea[e];
    } else {                       // self-loop for slice node
        dst = SL0 + (e - EE);
        src = dst;
        a = g_easum * (1.f / (float)EE);
    }
    return true;
}

__global__ void k_pass2(const int* __restrict__ ei, const float* __restrict__ ea,
                        const float* __restrict__ x) {
    int e = blockIdx.x * blockDim.x + threadIdx.x;
    if (e >= EE + NN) return;
    int src, dst; float a;
    if (!edge_fetch(e, ei, ea, src, dst, a)) return;
    int d = dst - SL0;
    float4 as = *(const float4*)&g_asrc[src * 4];
    float4 ad = *(const float4*)&g_adst[d * 4];
    float ex0 = __expf(lrelu(as.x + ad.x + a * g_kvec[0]));
    float ex1 = __expf(lrelu(as.y + ad.y + a * g_kvec[1]));
    float ex2 = __expf(lrelu(as.z + ad.z + a * g_kvec[2]));
    float ex3 = __expf(lrelu(as.w + ad.w + a * g_kvec[3]));
    atomicAdd(&((float4*)g_denom)[d], make_float4(ex0, ex1, ex2, ex3));

    const float4* xs = (const float4*)(x + src * FIN);
    float4* xa = &g_xacc[d * NH * 16];
    #pragma unroll
    for (int q = 0; q < 16; q++) {
        float4 xv = xs[q];
        atomicAdd(&xa[0 * 16 + q], make_float4(ex0 * xv.x, ex0 * xv.y, ex0 * xv.z, ex0 * xv.w));
        atomicAdd(&xa[1 * 16 + q], make_float4(ex1 * xv.x, ex1 * xv.y, ex1 * xv.z, ex1 * xv.w));
        atomicAdd(&xa[2 * 16 + q], make_float4(ex2 * xv.x, ex2 * xv.y, ex2 * xv.z, ex2 * xv.w));
        atomicAdd(&xa[3 * 16 + q], make_float4(ex3 * xv.x, ex3 * xv.y, ex3 * xv.z, ex3 * xv.w));
    }
}

// ---------------- k_gath: gat row = (xacc_h @ W_gat)/denom + bias, relu ------
__global__ void __launch_bounds__(128) k_gath(const float* __restrict__ W_gat,
                                              const float* __restrict__ gat_bias) {
    __shared__ float sx[NH * FIN];            // xacc row (256 floats)
    int j = threadIdx.x;
    int h = j >> 5;

    float Wc[FIN];
    #pragma unroll
    for (int f = 0; f < FIN; f++) Wc[f] = W_gat[f * HC + j];   // coalesced across j
    float gb = gat_bias[j];

    for (int d = blockIdx.x; d < NN; d += gridDim.x) {
        const float* xr = (const float*)&g_xacc[d * NH * 16];
        sx[j]       = xr[j];
        sx[128 + j] = xr[128 + j];
        __syncthreads();
        float den = g_denom[d * 4 + h];
        float s0 = 0.f, s1 = 0.f, s2 = 0.f, s3 = 0.f;
        const float4* sxh = (const float4*)&sx[h * FIN];
        #pragma unroll
        for (int q = 0; q < FIN / 4; q++) {
            float4 r = sxh[q];                // warp-uniform broadcast
            s0 = fmaf(r.x, Wc[4 * q + 0], s0);
            s1 = fmaf(r.y, Wc[4 * q + 1], s1);
            s2 = fmaf(r.z, Wc[4 * q + 2], s2);
            s3 = fmaf(r.w, Wc[4 * q + 3], s3);
        }
        float v = __fdividef((s0 + s1) + (s2 + s3), den + 1e-16f) + gb;
        g_gat[d * HC + j] = fmaxf(v, 0.f);
        __syncthreads();
    }
}

// ---------------- k_gatpre: gate GEMM (g_pre = relu_row @ W_ih.T + biases) ---
__global__ void __launch_bounds__(128) k_gatpre(
        const float* __restrict__ W_ih, const float* __restrict__ b_ih,
        const float* __restrict__ b_hh) {
    __shared__ float srow[HC];
    int j = threadIdx.x;

    float W[HC];
    const float4* wrow = (const float4*)(W_ih + j * HC);
    #pragma unroll
    for (int q = 0; q < HC / 4; q++) {
        float4 v = wrow[q];
        W[4 * q + 0] = v.x; W[4 * q + 1] = v.y; W[4 * q + 2] = v.z; W[4 * q + 3] = v.w;
    }
    float bj = b_ih[j] + b_hh[j];
    const float4* srow4 = (const float4*)srow;

    for (int d = blockIdx.x; d < NN; d += gridDim.x) {
        srow[j] = g_gat[d * HC + j];
        __syncthreads();
        float s0 = bj, s1 = 0.f, s2 = 0.f, s3 = 0.f;
        #pragma unroll
        for (int q = 0; q < HC / 4; q++) {
            float4 r = srow4[q];
            s0 = fmaf(r.x, W[4 * q + 0], s0);
            s1 = fmaf(r.y, W[4 * q + 1], s1);
            s2 = fmaf(r.z, W[4 * q + 2], s2);
            s3 = fmaf(r.w, W[4 * q + 3], s3);
        }
        g_pre[d * HC + j] = (s0 + s1) + (s2 + s3);
        __syncthreads();
    }
}

// ---------------- k_chainp: segmented parallel LSTM chain --------------------
struct ChainSmem {
    float act[2][HID][4];   // [parity][unit][gate]
    float h[4][HID];        // per-warp private hidden copy
};

__global__ void __launch_bounds__(128, 1) k_chainp(const float* __restrict__ W_hh) {
    int lane = threadIdx.x & 31;
    int g    = threadIdx.x >> 5;
    __shared__ ChainSmem s;

    int s0   = blockIdx.x * SEGL;
    if (s0 >= NN) return;
    int send = min(s0 + SEGL, NN);
    int wst  = max(0, s0 - WARM);

    float W[32];
    #pragma unroll
    for (int k = 0; k < 32; k++) W[k] = W_hh[(g * 32 + lane) * 32 + k];

    float sc = (g == 2) ? -2.f : -1.f;
    float m_ = (g == 2) ?  2.f :  1.f;
    float b_ = (g == 2) ? -1.f :  0.f;
    bool  g0 = (g == 0);

    float c = 0.f;
    s.h[g][lane] = 0.f;
    __syncwarp();

    const float* preg = g_pre + g * 32 + lane;
    float pc = preg[wst * HC];
    float pn = preg[(wst + 1) * HC];

    #pragma unroll 1
    for (int n = wst; n < send; n++) {
        int p = n & 1;
        float pf = preg[(n + 2) * HC];          // prefetch (pad rows cover end)

        float a0 = pc, a1 = 0.f, a2 = 0.f, a3 = 0.f;
        const float4* h4 = (const float4*)s.h[g];
        #pragma unroll
        for (int q = 0; q < 8; q++) {
            float4 hv = h4[q];
            a0 = fmaf(hv.x, W[4 * q + 0], a0);
            a1 = fmaf(hv.y, W[4 * q + 1], a1);
            a2 = fmaf(hv.z, W[4 * q + 2], a2);
            a3 = fmaf(hv.w, W[4 * q + 3], a3);
        }
        float a = (a0 + a1) + (a2 + a3);

        float t = __fdividef(1.f, 1.f + __expf(sc * a));
        s.act[p][lane][g] = fmaf(m_, t, b_);
        __syncthreads();

        float4 A = *(const float4*)s.act[p][lane];     // {i, f, g, o}
        c = fmaf(A.y, c, A.x * A.z);
        float th = __fdividef(2.f, 1.f + __expf(-2.f * c)) - 1.f;
        float hnew = A.w * th;
        if (g0 && n >= s0) g_hist[n * HID + lane] = hnew;
        s.h[g][lane] = hnew;
        __syncwarp();

        pc = pn; pn = pf;
    }
}

// ---------------- k_out: y = hist @ W_fc + b_fc -----------------------------
__global__ void k_out(const float* __restrict__ W_fc, const float* __restrict__ b_fc,
                      float* __restrict__ out) {
    int gw = (blockIdx.x * blockDim.x + threadIdx.x) >> 5;
    int lane = threadIdx.x & 31;
    if (gw >= NN) return;
    float v = g_hist[gw * HID + lane] * W_fc[lane];
    #pragma unroll
    for (int o = 16; o; o >>= 1) v += __shfl_down_sync(0xffffffffu, v, o);
    if (lane == 0) out[gw] = v + b_fc[0];
}

// ---------------- launch -----------------------------------------------------
extern "C" void kernel_launch(void* const* d_in, const int* in_sizes, int n_in,
                              void* d_out, int out_size) {
    const float* x_seq     = (const float*)d_in[0];
    const int*   edge_index= (const int*  )d_in[1];
    const float* edge_attr = (const float*)d_in[2];
    const float* W_gat     = (const float*)d_in[3];
    const float* att_src   = (const float*)d_in[4];
    const float* att_dst   = (const float*)d_in[5];
    const float* att_edge  = (const float*)d_in[6];
    const float* W_edge    = (const float*)d_in[7];
    const float* gat_bias  = (const float*)d_in[8];
    const float* W_ih      = (const float*)d_in[9];
    const float* W_hh      = (const float*)d_in[10];
    const float* b_ih      = (const float*)d_in[11];
    const float* b_hh      = (const float*)d_in[12];
    const float* W_fc      = (const float*)d_in[13];
    const float* b_fc      = (const float*)d_in[14];
    float* out = (float*)d_out;

    (void)in_sizes; (void)n_in; (void)out_size;

    k_init<<<INITB, 256>>>(W_edge, att_edge, edge_attr, W_gat, att_src, att_dst);
    k_alog<<<1480, 256>>>(x_seq);
    int eblocks = (EE + NN + 255) / 256;
    k_pass2<<<eblocks, 256>>>(edge_index, edge_attr, x_seq);
    k_gath<<<440, 128>>>(W_gat, gat_bias);
    k_gatpre<<<440, 128>>>(W_ih, b_ih, b_hh);
    k_chainp<<<NSEG, 128>>>(W_hh);
    k_out<<<(NN * 32 + 255) / 256, 256>>>(W_fc, b_fc, out);
}